// round 8
// baseline (speedup 1.0000x reference)
#include <cuda_runtime.h>
#include <cuda_bf16.h>
#include <cstdint>
#include <math.h>

// ---------------- problem constants ----------------
#define B_      64
#define V_      49
#define NPATCH  196
#define CIN     12
#define PSZ     16
#define IMG     224
#define ENC     768
#define DEC     512
#define NL      8
#define NH      16
#define HD      32
#define FFN     2048
#define OUTD    3072
#define ROWS_V  (B_ * V_)       // 3136
#define ROWS_N  (B_ * NPATCH)   // 12544

// ---------------- scratch ----------------
__device__ float g_patch[ROWS_V * OUTD];
__device__ float g_encr [ROWS_V * ENC];
__device__ float g_dec  [ROWS_V * DEC];
__device__ float g_h    [ROWS_N * DEC];
__device__ float g_hr   [ROWS_N * DEC];
__device__ float g_tmp  [ROWS_N * DEC];
__device__ float g_attn [ROWS_N * DEC];
__device__ float g_qkv  [ROWS_N * 3 * DEC];
__device__ float g_ffn  [ROWS_N * FFN];
__device__ float g_wt   [29491200];          // tf32-rounded weights, TRANSPOSED to [N,K]
__device__ int   g_visidx[B_ * V_];
__device__ int   g_src   [B_ * NPATCH];

// weight-scratch offsets (floats)
#define WT_WP   0
#define WT_E2D  2359296
#define WT_QKV  2752512
#define WT_O    9043968
#define WT_W1   11141120
#define WT_W2   19529728
#define WT_R    27918336

// ---------------- helpers ----------------
__device__ __forceinline__ float rna_tf32(float x) {
    uint32_t y;
    asm("cvt.rna.tf32.f32 %0, %1;" : "=r"(y) : "f"(x));
    return __uint_as_float(y);
}
__device__ __forceinline__ float gelu_exact(float v) {
    return 0.5f * v * (1.0f + erff(v * 0.7071067811865476f));
}
__device__ __forceinline__ void cp_async16(void* smem_dst, const void* gmem_src, bool pred) {
    uint32_t saddr = (uint32_t)__cvta_generic_to_shared(smem_dst);
    int sz = pred ? 16 : 0;
    asm volatile("cp.async.cg.shared.global [%0], [%1], 16, %2;\n"
                 :: "r"(saddr), "l"(gmem_src), "r"(sz));
}
__device__ __forceinline__ void mma_tf32(float* c, const uint32_t* a, const uint32_t* b) {
    asm volatile(
        "mma.sync.aligned.m16n8k8.row.col.f32.tf32.tf32.f32 "
        "{%0,%1,%2,%3}, {%4,%5,%6,%7}, {%8,%9}, {%0,%1,%2,%3};"
        : "+f"(c[0]), "+f"(c[1]), "+f"(c[2]), "+f"(c[3])
        : "r"(a[0]), "r"(a[1]), "r"(a[2]), "r"(a[3]), "r"(b[0]), "r"(b[1]));
}
__device__ __forceinline__ void ldsm4(uint32_t* r, uint32_t saddr) {
    asm volatile("ldmatrix.sync.aligned.m8n8.x4.shared.b16 {%0,%1,%2,%3}, [%4];"
                 : "=r"(r[0]), "=r"(r[1]), "=r"(r[2]), "=r"(r[3]) : "r"(saddr));
}

// ---------------- weight prep: transpose [K,N]->[N,K] + RNA-tf32 round ----------------
__global__ void transpose_round(const float* __restrict__ src, float* __restrict__ dst,
                                int K, int N) {
    __shared__ float t[32][33];
    int kb = blockIdx.y * 32, nb = blockIdx.x * 32;
    #pragma unroll
    for (int i = 0; i < 4; i++)
        t[threadIdx.y + 8 * i][threadIdx.x] =
            src[(size_t)(kb + threadIdx.y + 8 * i) * N + nb + threadIdx.x];
    __syncthreads();
    #pragma unroll
    for (int i = 0; i < 4; i++)
        dst[(size_t)(nb + threadIdx.y + 8 * i) * K + kb + threadIdx.x] =
            rna_tf32(t[threadIdx.x][threadIdx.y + 8 * i]);
}

// ---------------- mask scan ----------------
__global__ void scan_kernel(const int* __restrict__ mask) {
    int b = threadIdx.x;
    if (b >= B_) return;
    int cnt = 0;
    for (int n = 0; n < NPATCH; n++) {
        int m = mask[b * NPATCH + n];
        if (m == 0) {
            if (cnt < V_) g_visidx[b * V_ + cnt] = n;
            g_src[b * NPATCH + n] = (cnt < V_) ? cnt : (V_ - 1);
            cnt++;
        } else {
            g_src[b * NPATCH + n] = -1;
        }
    }
    for (int c = cnt; c < V_; c++) g_visidx[b * V_ + c] = 0;
}

// ---------------- patchify (rounded: feeds GEMM A only) ----------------
__global__ void patchify_kernel(const float* __restrict__ x) {
    int r  = blockIdx.x;
    int b  = r / V_;
    int n  = g_visidx[r];
    int hp = n / (IMG / PSZ);
    int wp = n % (IMG / PSZ);
    for (int f = threadIdx.x; f < OUTD; f += blockDim.x) {
        int c  = f >> 8;
        int ph = (f >> 4) & 15;
        int pw = f & 15;
        float v = x[((b * CIN + c) * IMG + hp * PSZ + ph) * IMG + wp * PSZ + pw];
        g_patch[r * OUTD + f] = rna_tf32(v);
    }
}

// ---------------- assemble: fp32 residual + rounded GEMM-A copy ----------------
__global__ void assemble_kernel(const float* __restrict__ mask_token,
                                const float* __restrict__ pos_embed) {
    int row = blockIdx.x;
    int b = row / NPATCH;
    int n = row % NPATCH;
    int s = g_src[row];
    const float4* src = (s >= 0)
        ? (const float4*)&g_dec[(b * V_ + s) * DEC]
        : (const float4*)mask_token;
    const float4* pos = (const float4*)&pos_embed[n * DEC];
    int t = threadIdx.x;
    float4 a = src[t], p = pos[t];
    float4 v = make_float4(a.x + p.x, a.y + p.y, a.z + p.z, a.w + p.w);
    ((float4*)&g_h[(size_t)row * DEC])[t] = v;
    ((float4*)&g_hr[(size_t)row * DEC])[t] =
        make_float4(rna_tf32(v.x), rna_tf32(v.y), rna_tf32(v.z), rna_tf32(v.w));
}

// ---------------- tf32 tensor-core GEMM: 128x64 tile, 3 CTAs/SM ----------
// C(MxN) = A(MxK) @ Wt(NxK)^T + bias [+resid] [gelu] ; optional rounded copy Cr.
// 256 threads = 8 warps as 4(m) x 2(n); warp tile 32x32.
#define BM 128
#define BN 64
#define BK 32
#define TSTRIDE 36
#define TILEAF (128 * TSTRIDE)       // 4608 floats
#define TILEBF (64 * TSTRIDE)        // 2304 floats
#define STAGEF (TILEAF + TILEBF)     // 6912 floats
#define GEMM_SMEM (2 * STAGEF * 4)   // 55296 B
#define FLAG_GELU  1
#define FLAG_ROUND 2

__device__ __forceinline__ void gemm_load_stage(
    const float* __restrict__ A, const float* __restrict__ Wt,
    float* sm, int s, int c, int bm, int bn, int M, int K, int t)
{
    float* base = sm + s * STAGEF;
    int k0 = c * BK;
    #pragma unroll
    for (int i = 0; i < 6; i++) {
        int idx = t + (i << 8);           // 0..1535 (each 16B)
        const float* src;
        float* dst;
        int ok = 1;
        if (idx < 1024) {                 // A: 128 rows x 8 chunks
            int row = idx >> 3, c16 = idx & 7;
            int gr = bm + row;
            if (gr >= M) { ok = 0; gr = M - 1; }
            src = A + (size_t)gr * K + k0 + c16 * 4;
            dst = base + row * TSTRIDE + c16 * 4;
        } else {                          // B: 64 rows x 8 chunks
            int bidx = idx - 1024;
            int row = bidx >> 3, c16 = bidx & 7;
            src = Wt + (size_t)(bn + row) * K + k0 + c16 * 4;
            dst = base + TILEAF + row * TSTRIDE + c16 * 4;
        }
        cp_async16(dst, src, ok);
    }
    asm volatile("cp.async.commit_group;\n");
}

__global__ __launch_bounds__(256, 3) void gemm_tc_kernel(
    const float* __restrict__ A, const float* __restrict__ Wt,
    const float* __restrict__ bias, const float* __restrict__ resid,
    float* __restrict__ C, float* __restrict__ Cr,
    int M, int N, int K, int flags)
{
    extern __shared__ float sm[];

    const int t = threadIdx.x;
    const int bn = blockIdx.x * BN;
    const int bm = blockIdx.y * BM;
    const int warp = t >> 5, lane = t & 31;
    const int wm = warp >> 1, wn = warp & 1;
    const int lq = lane >> 2, lr = lane & 3;
    const int g  = lane >> 3;            // ldmatrix group 0..3
    const int gr = lane & 7;

    float acc[2][4][4] = {};

    const int nch = K / BK;
    gemm_load_stage(A, Wt, sm, 0, 0, bm, bn, M, K, t);

    // ldmatrix per-thread bases (floats)
    const int a_row = wm * 32 + (g & 1) * 8 + gr;
    const int a_col = (g >> 1) * 4;
    const int b_row = wn * 32 + (g >> 1) * 8 + gr;
    const int b_col = (g & 1) * 4;

    for (int c = 0; c < nch; c++) {
        int s = c & 1;
        if (c + 1 < nch) {
            gemm_load_stage(A, Wt, sm, s ^ 1, c + 1, bm, bn, M, K, t);
            asm volatile("cp.async.wait_group 1;\n");
        } else {
            asm volatile("cp.async.wait_group 0;\n");
        }
        __syncthreads();

        const float* Ab = sm + s * STAGEF;
        const float* Bb = Ab + TILEAF;
        uint32_t a_base = (uint32_t)__cvta_generic_to_shared(Ab + a_row * TSTRIDE + a_col);
        uint32_t b_base = (uint32_t)__cvta_generic_to_shared(Bb + b_row * TSTRIDE + b_col);

        #pragma unroll
        for (int ks = 0; ks < 4; ks++) {
            const int k = ks * 8;
            uint32_t af[2][4];
            uint32_t bf[4][2];
            #pragma unroll
            for (int mi = 0; mi < 2; mi++)
                ldsm4(af[mi], a_base + (mi * 16 * TSTRIDE + k) * 4);
            #pragma unroll
            for (int p = 0; p < 2; p++) {
                uint32_t r[4];
                ldsm4(r, b_base + (p * 16 * TSTRIDE + k) * 4);
                bf[p * 2 + 0][0] = r[0]; bf[p * 2 + 0][1] = r[1];
                bf[p * 2 + 1][0] = r[2]; bf[p * 2 + 1][1] = r[3];
            }
            #pragma unroll
            for (int mi = 0; mi < 2; mi++)
                #pragma unroll
                for (int ni = 0; ni < 4; ni++)
                    mma_tf32(acc[mi][ni], af[mi], bf[ni]);
        }
        __syncthreads();
    }

    const bool dogelu  = (flags & FLAG_GELU) != 0;
    const bool doround = (flags & FLAG_ROUND) != 0;

    #pragma unroll
    for (int mi = 0; mi < 2; mi++) {
        int r0 = bm + wm * 32 + mi * 16 + lq;
        #pragma unroll
        for (int ni = 0; ni < 4; ni++) {
            int col = bn + wn * 32 + ni * 8 + lr * 2;
            float bx = bias[col], by = bias[col + 1];
            float* a4 = acc[mi][ni];
            #pragma unroll
            for (int half = 0; half < 2; half++) {
                int r = r0 + half * 8;
                if (r >= M) continue;
                float vx = a4[half * 2 + 0] + bx;
                float vy = a4[half * 2 + 1] + by;
                if (resid) {
                    const float* rr = resid + (size_t)r * N + col;
                    vx += rr[0]; vy += rr[1];
                }
                if (dogelu) { vx = gelu_exact(vx); vy = gelu_exact(vy); }
                float ox = vx, oy = vy;
                if (doround) { ox = rna_tf32(vx); oy = rna_tf32(vy); }
                *(float2*)(C + (size_t)r * N + col) = make_float2(ox, oy);
                if (Cr)
                    *(float2*)(Cr + (size_t)r * N + col) =
                        make_float2(rna_tf32(vx), rna_tf32(vy));
            }
        }
    }
}

// ---------------- layernorm: fp32 out + rounded out ----------------
__global__ __launch_bounds__(128) void ln_kernel(
    const float* __restrict__ in, float* __restrict__ out, float* __restrict__ outr,
    const float* __restrict__ gamma, const float* __restrict__ beta)
{
    __shared__ float red[8];
    int row = blockIdx.x;
    int t = threadIdx.x;
    float4 v = ((const float4*)(in + (size_t)row * DEC))[t];
    float s  = v.x + v.y + v.z + v.w;
    float sq = v.x * v.x + v.y * v.y + v.z * v.z + v.w * v.w;
    #pragma unroll
    for (int off = 16; off > 0; off >>= 1) {
        s  += __shfl_xor_sync(0xffffffff, s,  off);
        sq += __shfl_xor_sync(0xffffffff, sq, off);
    }
    int w = t >> 5;
    if ((t & 31) == 0) { red[w] = s; red[4 + w] = sq; }
    __syncthreads();
    s  = red[0] + red[1] + red[2] + red[3];
    sq = red[4] + red[5] + red[6] + red[7];
    float mu = s * (1.0f / DEC);
    float var = sq * (1.0f / DEC) - mu * mu;
    float rstd = rsqrtf(var + 1e-5f);
    float4 g = ((const float4*)gamma)[t];
    float4 b = ((const float4*)beta)[t];
    float4 o;
    o.x = (v.x - mu) * rstd * g.x + b.x;
    o.y = (v.y - mu) * rstd * g.y + b.y;
    o.z = (v.z - mu) * rstd * g.z + b.z;
    o.w = (v.w - mu) * rstd * g.w + b.w;
    ((float4*)(out + (size_t)row * DEC))[t] = o;
    ((float4*)(outr + (size_t)row * DEC))[t] =
        make_float4(rna_tf32(o.x), rna_tf32(o.y), rna_tf32(o.z), rna_tf32(o.w));
}

// ---------------- attention ----------------
#define KSTRIDE 33
#define SM_K 0
#define SM_V (NPATCH * KSTRIDE)
#define SM_P (SM_V + NPATCH * HD)
#define ATTN_SMEM ((SM_P + 8 * NPATCH) * 4)

__global__ __launch_bounds__(256) void attn_kernel() {
    extern __shared__ float smf[];
    float* Ksm = smf + SM_K;
    float* Vsm = smf + SM_V;
    float* Psm = smf + SM_P;

    int bh = blockIdx.x;
    int b = bh >> 4;
    int h = bh & 15;
    const float* qkv = g_qkv + (size_t)b * (NPATCH * 3 * DEC);
    int tid = threadIdx.x;

    for (int idx = tid; idx < NPATCH * HD; idx += 256) {
        int j = idx >> 5, d = idx & 31;
        Ksm[j * KSTRIDE + d] = qkv[j * (3 * DEC) + DEC     + h * HD + d];
        Vsm[j * HD      + d] = qkv[j * (3 * DEC) + 2 * DEC + h * HD + d];
    }
    __syncthreads();

    int warp = tid >> 5, lane = tid & 31;
    const float scale = 0.17677669529663687f;

    for (int i = warp; i < NPATCH; i += 8) {
        const float* q = qkv + i * (3 * DEC) + h * HD;
        float qr[HD];
        #pragma unroll
        for (int kk = 0; kk < HD; kk++) qr[kk] = q[kk];

        float s[7];
        float mx = -1e30f;
        #pragma unroll
        for (int jj = 0; jj < 7; jj++) {
            int j = jj * 32 + lane;
            float acc = -1e30f;
            if (j < NPATCH) {
                acc = 0.f;
                #pragma unroll
                for (int kk = 0; kk < HD; kk++) acc += qr[kk] * Ksm[j * KSTRIDE + kk];
                acc *= scale;
            }
            s[jj] = acc;
            mx = fmaxf(mx, acc);
        }
        #pragma unroll
        for (int off = 16; off > 0; off >>= 1)
            mx = fmaxf(mx, __shfl_xor_sync(0xffffffff, mx, off));

        float sum = 0.f;
        #pragma unroll
        for (int jj = 0; jj < 7; jj++) {
            int j = jj * 32 + lane;
            float p = (j < NPATCH) ? __expf(s[jj] - mx) : 0.f;
            if (j < NPATCH) Psm[warp * NPATCH + j] = p;
            sum += p;
        }
        #pragma unroll
        for (int off = 16; off > 0; off >>= 1)
            sum += __shfl_xor_sync(0xffffffff, sum, off);
        float inv = 1.0f / sum;
        __syncwarp();

        const float* pp = Psm + warp * NPATCH;
        float a0 = 0.f, a1 = 0.f, a2 = 0.f, a3 = 0.f;
        for (int j = 0; j < NPATCH; j += 4) {
            a0 += pp[j]     * Vsm[j * HD + lane];
            a1 += pp[j + 1] * Vsm[(j + 1) * HD + lane];
            a2 += pp[j + 2] * Vsm[(j + 2) * HD + lane];
            a3 += pp[j + 3] * Vsm[(j + 3) * HD + lane];
        }
        float acc = (a0 + a1) + (a2 + a3);
        g_attn[((size_t)b * NPATCH + i) * DEC + h * HD + lane] = rna_tf32(acc * inv);
        __syncwarp();
    }
}

// ---------------- host launchers ----------------
static inline void launch_gemm(const float* A, const float* Wt, const float* bias,
                               const float* resid, float* C, float* Cr,
                               int M, int N, int K, int flags) {
    dim3 grid(N / BN, (M + BM - 1) / BM);
    gemm_tc_kernel<<<grid, 256, GEMM_SMEM>>>(A, Wt, bias, resid, C, Cr, M, N, K, flags);
}
static inline void launch_tr(const float* src, float* dst, int K, int N) {
    dim3 grid(N / 32, K / 32), blk(32, 8);
    transpose_round<<<grid, blk>>>(src, dst, K, N);
}

extern "C" void kernel_launch(void* const* d_in, const int* in_sizes, int n_in,
                              void* d_out, int out_size) {
    const float* x          = (const float*)d_in[0];
    const int*   mask       = (const int*)  d_in[1];
    const float* Wp         = (const float*)d_in[3];
    const float* bp         = (const float*)d_in[4];
    const float* We2d       = (const float*)d_in[5];
    const float* be2d       = (const float*)d_in[6];
    const float* mask_token = (const float*)d_in[7];
    const float* pos_embed  = (const float*)d_in[8];
    const float* Wqkv       = (const float*)d_in[9];
    const float* bqkv       = (const float*)d_in[10];
    const float* Wo         = (const float*)d_in[11];
    const float* bo         = (const float*)d_in[12];
    const float* ln1g       = (const float*)d_in[13];
    const float* ln1b       = (const float*)d_in[14];
    const float* W1         = (const float*)d_in[15];
    const float* b1         = (const float*)d_in[16];
    const float* W2         = (const float*)d_in[17];
    const float* b2         = (const float*)d_in[18];
    const float* ln2g       = (const float*)d_in[19];
    const float* ln2b       = (const float*)d_in[20];
    const float* Wr         = (const float*)d_in[21];
    const float* br         = (const float*)d_in[22];

    float* out = (float*)d_out;
    float* rec = out;
    float* enc = out + (size_t)ROWS_N * OUTD;

    float *p_patch, *p_encr, *p_dec, *p_h, *p_hr, *p_tmp, *p_attn, *p_qkv, *p_ffn, *p_wt;
    cudaGetSymbolAddress((void**)&p_patch, g_patch);
    cudaGetSymbolAddress((void**)&p_encr,  g_encr);
    cudaGetSymbolAddress((void**)&p_dec,   g_dec);
    cudaGetSymbolAddress((void**)&p_h,     g_h);
    cudaGetSymbolAddress((void**)&p_hr,    g_hr);
    cudaGetSymbolAddress((void**)&p_tmp,   g_tmp);
    cudaGetSymbolAddress((void**)&p_attn,  g_attn);
    cudaGetSymbolAddress((void**)&p_qkv,   g_qkv);
    cudaGetSymbolAddress((void**)&p_ffn,   g_ffn);
    cudaGetSymbolAddress((void**)&p_wt,    g_wt);

    cudaFuncSetAttribute(attn_kernel, cudaFuncAttributeMaxDynamicSharedMemorySize, ATTN_SMEM);
    cudaFuncSetAttribute(gemm_tc_kernel, cudaFuncAttributeMaxDynamicSharedMemorySize, GEMM_SMEM);

    // weight prep: transpose to [N,K] + RNA-tf32 round
    launch_tr(Wp,   p_wt + WT_WP,  OUTD, ENC);
    launch_tr(We2d, p_wt + WT_E2D, ENC,  DEC);
    for (int l = 0; l < NL; l++) {
        launch_tr(Wqkv + (size_t)l * DEC * 3 * DEC, p_wt + WT_QKV + (size_t)l * 3 * DEC * DEC, DEC, 3 * DEC);
        launch_tr(Wo   + (size_t)l * DEC * DEC,     p_wt + WT_O   + (size_t)l * DEC * DEC,     DEC, DEC);
        launch_tr(W1   + (size_t)l * DEC * FFN,     p_wt + WT_W1  + (size_t)l * DEC * FFN,     DEC, FFN);
        launch_tr(W2   + (size_t)l * FFN * DEC,     p_wt + WT_W2  + (size_t)l * FFN * DEC,     FFN, DEC);
    }
    launch_tr(Wr, p_wt + WT_R, DEC, OUTD);

    scan_kernel<<<1, 64>>>(mask);
    patchify_kernel<<<ROWS_V, 256>>>(x);

    launch_gemm(p_patch, p_wt + WT_WP, bp, nullptr, enc, p_encr, ROWS_V, ENC, OUTD, 0);
    launch_gemm(p_encr, p_wt + WT_E2D, be2d, nullptr, p_dec, nullptr, ROWS_V, DEC, ENC, 0);
    assemble_kernel<<<ROWS_N, 128>>>(mask_token, pos_embed);

    for (int l = 0; l < NL; l++) {
        const float* wt_qkv = p_wt + WT_QKV + (size_t)l * 3 * DEC * DEC;
        const float* wt_o   = p_wt + WT_O   + (size_t)l * DEC * DEC;
        const float* wt_1   = p_wt + WT_W1  + (size_t)l * DEC * FFN;
        const float* wt_2   = p_wt + WT_W2  + (size_t)l * FFN * DEC;
        const float* bq  = bqkv + (size_t)l * 3 * DEC;
        const float* bol = bo   + (size_t)l * DEC;
        const float* b1l = b1   + (size_t)l * FFN;
        const float* b2l = b2   + (size_t)l * DEC;

        launch_gemm(p_hr, wt_qkv, bq, nullptr, p_qkv, nullptr, ROWS_N, 3 * DEC, DEC, 0);
        attn_kernel<<<B_ * NH, 256, ATTN_SMEM>>>();
        launch_gemm(p_attn, wt_o, bol, p_h, p_tmp, nullptr, ROWS_N, DEC, DEC, 0);
        ln_kernel<<<ROWS_N, 128>>>(p_tmp, p_h, p_hr, ln1g + l * DEC, ln1b + l * DEC);
        launch_gemm(p_hr, wt_1, b1l, nullptr, p_ffn, nullptr, ROWS_N, FFN, DEC,
                    FLAG_GELU | FLAG_ROUND);
        launch_gemm(p_ffn, wt_2, b2l, p_h, p_tmp, nullptr, ROWS_N, DEC, FFN, 0);
        ln_kernel<<<ROWS_N, 128>>>(p_tmp, p_h, p_hr, ln2g + l * DEC, ln2b + l * DEC);
    }

    launch_gemm(p_hr, p_wt + WT_R, br, nullptr, rec, nullptr, ROWS_N, OUTD, DEC, 0);
}

// round 10
// speedup vs baseline: 1.3155x; 1.3155x over previous
#include <cuda_runtime.h>
#include <cuda_fp16.h>
#include <cstdint>
#include <math.h>

// ---------------- problem constants ----------------
#define B_      64
#define V_      49
#define NPATCH  196
#define CIN     12
#define PSZ     16
#define IMG     224
#define ENC     768
#define DEC     512
#define NL      8
#define NH      16
#define HD      32
#define FFN     2048
#define OUTD    3072
#define ROWS_V  (B_ * V_)       // 3136
#define ROWS_N  (B_ * NPATCH)   // 12544

// ---------------- scratch ----------------
__device__ __half g_patchh[ROWS_V * OUTD];
__device__ __half g_ench  [ROWS_V * ENC];
__device__ float  g_dec   [ROWS_V * DEC];
__device__ float  g_h     [ROWS_N * DEC];
__device__ __half g_hh    [ROWS_N * DEC];
__device__ float  g_tmp   [ROWS_N * DEC];
__device__ __half g_attnh [ROWS_N * DEC];
__device__ float  g_qkv   [ROWS_N * 3 * DEC];
__device__ __half g_ffnh  [ROWS_N * FFN];
__device__ __half g_wh    [29491200];        // fp16 weights, TRANSPOSED to [N,K]
__device__ int    g_visidx[B_ * V_];
__device__ int    g_src   [B_ * NPATCH];

// weight-scratch offsets (halfs)
#define WT_WP   0
#define WT_E2D  2359296
#define WT_QKV  2752512
#define WT_O    9043968
#define WT_W1   11141120
#define WT_W2   19529728
#define WT_R    27918336

// ---------------- helpers ----------------
__device__ __forceinline__ float gelu_exact(float v) {
    return 0.5f * v * (1.0f + erff(v * 0.7071067811865476f));
}
__device__ __forceinline__ void cp_async16(void* smem_dst, const void* gmem_src, bool pred) {
    uint32_t saddr = (uint32_t)__cvta_generic_to_shared(smem_dst);
    int sz = pred ? 16 : 0;
    asm volatile("cp.async.cg.shared.global [%0], [%1], 16, %2;\n"
                 :: "r"(saddr), "l"(gmem_src), "r"(sz));
}
__device__ __forceinline__ void mma_f16(float* c, const uint32_t* a, const uint32_t* b) {
    asm volatile(
        "mma.sync.aligned.m16n8k16.row.col.f32.f16.f16.f32 "
        "{%0,%1,%2,%3}, {%4,%5,%6,%7}, {%8,%9}, {%0,%1,%2,%3};"
        : "+f"(c[0]), "+f"(c[1]), "+f"(c[2]), "+f"(c[3])
        : "r"(a[0]), "r"(a[1]), "r"(a[2]), "r"(a[3]), "r"(b[0]), "r"(b[1]));
}
__device__ __forceinline__ void ldsm4(uint32_t* r, uint32_t saddr) {
    asm volatile("ldmatrix.sync.aligned.m8n8.x4.shared.b16 {%0,%1,%2,%3}, [%4];"
                 : "=r"(r[0]), "=r"(r[1]), "=r"(r[2]), "=r"(r[3]) : "r"(saddr));
}

// ---------------- weight prep: transpose [K,N]->[N,K] + fp16 round ----------------
__global__ void transpose_half(const float* __restrict__ src, __half* __restrict__ dst,
                               int K, int N) {
    __shared__ float t[32][33];
    int kb = blockIdx.y * 32, nb = blockIdx.x * 32;
    #pragma unroll
    for (int i = 0; i < 4; i++)
        t[threadIdx.y + 8 * i][threadIdx.x] =
            src[(size_t)(kb + threadIdx.y + 8 * i) * N + nb + threadIdx.x];
    __syncthreads();
    #pragma unroll
    for (int i = 0; i < 4; i++)
        dst[(size_t)(nb + threadIdx.y + 8 * i) * K + kb + threadIdx.x] =
            __float2half_rn(t[threadIdx.x][threadIdx.y + 8 * i]);
}

// ---------------- mask scan ----------------
__global__ void scan_kernel(const int* __restrict__ mask) {
    int b = threadIdx.x;
    if (b >= B_) return;
    int cnt = 0;
    for (int n = 0; n < NPATCH; n++) {
        int m = mask[b * NPATCH + n];
        if (m == 0) {
            if (cnt < V_) g_visidx[b * V_ + cnt] = n;
            g_src[b * NPATCH + n] = (cnt < V_) ? cnt : (V_ - 1);
            cnt++;
        } else {
            g_src[b * NPATCH + n] = -1;
        }
    }
    for (int c = cnt; c < V_; c++) g_visidx[b * V_ + c] = 0;
}

// ---------------- patchify -> fp16 ----------------
__global__ void patchify_kernel(const float* __restrict__ x) {
    int r  = blockIdx.x;
    int b  = r / V_;
    int n  = g_visidx[r];
    int hp = n / (IMG / PSZ);
    int wp = n % (IMG / PSZ);
    for (int f = threadIdx.x; f < OUTD; f += blockDim.x) {
        int c  = f >> 8;
        int ph = (f >> 4) & 15;
        int pw = f & 15;
        float v = x[((b * CIN + c) * IMG + hp * PSZ + ph) * IMG + wp * PSZ + pw];
        g_patchh[(size_t)r * OUTD + f] = __float2half_rn(v);
    }
}

// ---------------- assemble: fp32 residual + fp16 GEMM-A copy ----------------
__global__ void assemble_kernel(const float* __restrict__ mask_token,
                                const float* __restrict__ pos_embed) {
    int row = blockIdx.x;
    int b = row / NPATCH;
    int n = row % NPATCH;
    int s = g_src[row];
    const float4* src = (s >= 0)
        ? (const float4*)&g_dec[(b * V_ + s) * DEC]
        : (const float4*)mask_token;
    const float4* pos = (const float4*)&pos_embed[n * DEC];
    int t = threadIdx.x;
    float4 a = src[t], p = pos[t];
    float4 v = make_float4(a.x + p.x, a.y + p.y, a.z + p.z, a.w + p.w);
    ((float4*)&g_h[(size_t)row * DEC])[t] = v;
    __half2* hh = (__half2*)&g_hh[(size_t)row * DEC];
    hh[t * 2 + 0] = __floats2half2_rn(v.x, v.y);
    hh[t * 2 + 1] = __floats2half2_rn(v.z, v.w);
}

// ---------------- fp16 tensor-core GEMM ----------------
// C(MxN)[fp32, optional] (+Ch fp16 optional) = A(MxK,h) @ Wt(NxK,h)^T + bias [+resid] [gelu]
// 128x128 tile, BK=32, 3-stage, 8 warps (2m x 4n), warp tile 64x32.
#define BM 128
#define BN 128
#define BK 32
#define STRH 40                          // halfs per smem row (32 + pad 8) = 80 B, 16B-aligned
#define TILEH (128 * STRH)               // 5120 halfs per tile
#define STAGEH (2 * TILEH)               // A + B
#define NSTAGE 3
#define GEMM_SMEM (NSTAGE * STAGEH * 2)  // 61440 B
#define FLAG_GELU 1

__device__ __forceinline__ void gemm_load_stage(
    const __half* __restrict__ A, const __half* __restrict__ Wt,
    __half* sm, int s, int c, int bm, int bn, int M, int K, int t)
{
    __half* base = sm + s * STAGEH;
    int k0 = c * BK;
    #pragma unroll
    for (int i = 0; i < 4; i++) {
        int idx = t + (i << 8);              // 0..1023 (16B = 8 halfs each)
        int part = idx >> 9;                 // 0 = A, 1 = B
        int sub  = idx & 511;
        int row  = sub >> 2;                 // 0..127
        int c8   = sub & 3;                  // 0..3
        const __half* src;
        int ok = 1;
        if (part == 0) {
            int gr = bm + row;
            if (gr >= M) { ok = 0; gr = M - 1; }
            src = A + (size_t)gr * K + k0 + c8 * 8;
        } else {
            src = Wt + (size_t)(bn + row) * K + k0 + c8 * 8;
        }
        cp_async16(base + part * TILEH + row * STRH + c8 * 8, src, ok);
    }
    asm volatile("cp.async.commit_group;\n");
}

__global__ __launch_bounds__(256, 2) void gemm_tc_kernel(
    const __half* __restrict__ A, const __half* __restrict__ Wt,
    const float* __restrict__ bias, const float* __restrict__ resid,
    float* __restrict__ C, __half* __restrict__ Ch,
    int M, int N, int K, int flags)
{
    extern __shared__ __half sm[];

    const int t = threadIdx.x;
    const int bn = blockIdx.x * BN;
    const int bm = blockIdx.y * BM;
    const int warp = t >> 5, lane = t & 31;
    const int wm = warp >> 2, wn = warp & 3;     // 2 x 4 warps, warp tile 64x32
    const int lq = lane >> 2, lr = lane & 3;
    const int g  = lane >> 3;                    // ldmatrix group 0..3
    const int gr = lane & 7;

    float acc[4][4][4] = {};

    const int nch = K / BK;
    gemm_load_stage(A, Wt, sm, 0, 0, bm, bn, M, K, t);
    gemm_load_stage(A, Wt, sm, 1, 1, bm, bn, M, K, t);

    // ldmatrix per-thread base offsets (halfs)
    // A x4 for mi-tile (m16 x k16): g0=(m0-7,k0-7) g1=(m8-15,k0-7) g2=(m0-7,k8-15) g3=(m8-15,k8-15)
    const int a_off = (wm * 64 + (g & 1) * 8 + gr) * STRH + (g >> 1) * 8;
    // B x4 over 4 n8-tiles at one k8-column: group g = n-tile g
    const int b_off = (wn * 32 + g * 8 + gr) * STRH;

    for (int c = 0; c < nch; c++) {
        int s = c - (c / NSTAGE) * NSTAGE;
        if (c + 1 < nch) asm volatile("cp.async.wait_group 1;\n");
        else             asm volatile("cp.async.wait_group 0;\n");
        __syncthreads();
        if (c + 2 < nch) {
            int s2 = (c + 2) - ((c + 2) / NSTAGE) * NSTAGE;
            gemm_load_stage(A, Wt, sm, s2, c + 2, bm, bn, M, K, t);
        }

        const __half* Ab = sm + s * STAGEH;
        const __half* Bb = Ab + TILEH;
        uint32_t a_base = (uint32_t)__cvta_generic_to_shared(Ab + a_off);
        uint32_t b_base = (uint32_t)__cvta_generic_to_shared(Bb + b_off);

        #pragma unroll
        for (int ks = 0; ks < 2; ks++) {          // two k16 steps per BK=32 chunk
            const int kh = ks * 16;
            uint32_t af[4][4];
            uint32_t b0[4], b1[4];
            #pragma unroll
            for (int mi = 0; mi < 4; mi++)
                ldsm4(af[mi], a_base + (mi * 16 * STRH + kh) * 2);
            ldsm4(b0, b_base + (kh + 0) * 2);     // k 0-7 of this step, 4 n-tiles
            ldsm4(b1, b_base + (kh + 8) * 2);     // k 8-15
            #pragma unroll
            for (int mi = 0; mi < 4; mi++)
                #pragma unroll
                for (int ni = 0; ni < 4; ni++) {
                    uint32_t bf[2] = { b0[ni], b1[ni] };
                    mma_f16(acc[mi][ni], af[mi], bf);
                }
        }
    }

    __syncthreads();
    const bool dogelu = (flags & FLAG_GELU) != 0;

    #pragma unroll
    for (int mi = 0; mi < 4; mi++) {
        int r0 = bm + wm * 64 + mi * 16 + lq;
        #pragma unroll
        for (int ni = 0; ni < 4; ni++) {
            int col = bn + wn * 32 + ni * 8 + lr * 2;
            float bx = bias[col], by = bias[col + 1];
            float* a4 = acc[mi][ni];
            #pragma unroll
            for (int half = 0; half < 2; half++) {
                int r = r0 + half * 8;
                if (r >= M) continue;
                float vx = a4[half * 2 + 0] + bx;
                float vy = a4[half * 2 + 1] + by;
                if (resid) {
                    const float* rr = resid + (size_t)r * N + col;
                    vx += rr[0]; vy += rr[1];
                }
                if (dogelu) { vx = gelu_exact(vx); vy = gelu_exact(vy); }
                if (C)
                    *(float2*)(C + (size_t)r * N + col) = make_float2(vx, vy);
                if (Ch)
                    *(__half2*)(Ch + (size_t)r * N + col) = __floats2half2_rn(vx, vy);
            }
        }
    }
}

// ---------------- layernorm: fp32 out + fp16 out ----------------
__global__ __launch_bounds__(128) void ln_kernel(
    const float* __restrict__ in, float* __restrict__ out, __half* __restrict__ outh,
    const float* __restrict__ gamma, const float* __restrict__ beta)
{
    __shared__ float red[8];
    int row = blockIdx.x;
    int t = threadIdx.x;
    float4 v = ((const float4*)(in + (size_t)row * DEC))[t];
    float s  = v.x + v.y + v.z + v.w;
    float sq = v.x * v.x + v.y * v.y + v.z * v.z + v.w * v.w;
    #pragma unroll
    for (int off = 16; off > 0; off >>= 1) {
        s  += __shfl_xor_sync(0xffffffff, s,  off);
        sq += __shfl_xor_sync(0xffffffff, sq, off);
    }
    int w = t >> 5;
    if ((t & 31) == 0) { red[w] = s; red[4 + w] = sq; }
    __syncthreads();
    s  = red[0] + red[1] + red[2] + red[3];
    sq = red[4] + red[5] + red[6] + red[7];
    float mu = s * (1.0f / DEC);
    float var = sq * (1.0f / DEC) - mu * mu;
    float rstd = rsqrtf(var + 1e-5f);
    float4 g = ((const float4*)gamma)[t];
    float4 b = ((const float4*)beta)[t];
    float4 o;
    o.x = (v.x - mu) * rstd * g.x + b.x;
    o.y = (v.y - mu) * rstd * g.y + b.y;
    o.z = (v.z - mu) * rstd * g.z + b.z;
    o.w = (v.w - mu) * rstd * g.w + b.w;
    ((float4*)(out + (size_t)row * DEC))[t] = o;
    __half2* hh = (__half2*)(outh + (size_t)row * DEC);
    hh[t * 2 + 0] = __floats2half2_rn(o.x, o.y);
    hh[t * 2 + 1] = __floats2half2_rn(o.z, o.w);
}

// ---------------- attention ----------------
#define KSTRIDE 33
#define SM_K 0
#define SM_V (NPATCH * KSTRIDE)
#define SM_P (SM_V + NPATCH * HD)
#define ATTN_SMEM ((SM_P + 8 * NPATCH) * 4)

__global__ __launch_bounds__(256) void attn_kernel() {
    extern __shared__ float smf[];
    float* Ksm = smf + SM_K;
    float* Vsm = smf + SM_V;
    float* Psm = smf + SM_P;

    int bh = blockIdx.x;
    int b = bh >> 4;
    int h = bh & 15;
    const float* qkv = g_qkv + (size_t)b * (NPATCH * 3 * DEC);
    int tid = threadIdx.x;

    for (int idx = tid; idx < NPATCH * HD; idx += 256) {
        int j = idx >> 5, d = idx & 31;
        Ksm[j * KSTRIDE + d] = qkv[j * (3 * DEC) + DEC     + h * HD + d];
        Vsm[j * HD      + d] = qkv[j * (3 * DEC) + 2 * DEC + h * HD + d];
    }
    __syncthreads();

    int warp = tid >> 5, lane = tid & 31;
    const float scale = 0.17677669529663687f;

    for (int i = warp; i < NPATCH; i += 8) {
        const float* q = qkv + i * (3 * DEC) + h * HD;
        float qr[HD];
        #pragma unroll
        for (int kk = 0; kk < HD; kk++) qr[kk] = q[kk];

        float s[7];
        float mx = -1e30f;
        #pragma unroll
        for (int jj = 0; jj < 7; jj++) {
            int j = jj * 32 + lane;
            float acc = -1e30f;
            if (j < NPATCH) {
                acc = 0.f;
                #pragma unroll
                for (int kk = 0; kk < HD; kk++) acc += qr[kk] * Ksm[j * KSTRIDE + kk];
                acc *= scale;
            }
            s[jj] = acc;
            mx = fmaxf(mx, acc);
        }
        #pragma unroll
        for (int off = 16; off > 0; off >>= 1)
            mx = fmaxf(mx, __shfl_xor_sync(0xffffffff, mx, off));

        float sum = 0.f;
        #pragma unroll
        for (int jj = 0; jj < 7; jj++) {
            int j = jj * 32 + lane;
            float p = (j < NPATCH) ? __expf(s[jj] - mx) : 0.f;
            if (j < NPATCH) Psm[warp * NPATCH + j] = p;
            sum += p;
        }
        #pragma unroll
        for (int off = 16; off > 0; off >>= 1)
            sum += __shfl_xor_sync(0xffffffff, sum, off);
        float inv = 1.0f / sum;
        __syncwarp();

        const float* pp = Psm + warp * NPATCH;
        float a0 = 0.f, a1 = 0.f, a2 = 0.f, a3 = 0.f;
        for (int j = 0; j < NPATCH; j += 4) {
            a0 += pp[j]     * Vsm[j * HD + lane];
            a1 += pp[j + 1] * Vsm[(j + 1) * HD + lane];
            a2 += pp[j + 2] * Vsm[(j + 2) * HD + lane];
            a3 += pp[j + 3] * Vsm[(j + 3) * HD + lane];
        }
        float acc = (a0 + a1) + (a2 + a3);
        g_attnh[((size_t)b * NPATCH + i) * DEC + h * HD + lane] = __float2half_rn(acc * inv);
        __syncwarp();
    }
}

// ---------------- host launchers ----------------
static inline void launch_gemm(const __half* A, const __half* Wt, const float* bias,
                               const float* resid, float* C, __half* Ch,
                               int M, int N, int K, int flags) {
    dim3 grid(N / BN, (M + BM - 1) / BM);
    gemm_tc_kernel<<<grid, 256, GEMM_SMEM>>>(A, Wt, bias, resid, C, Ch, M, N, K, flags);
}
static inline void launch_tr(const float* src, __half* dst, int K, int N) {
    dim3 grid(N / 32, K / 32), blk(32, 8);
    transpose_half<<<grid, blk>>>(src, dst, K, N);
}

extern "C" void kernel_launch(void* const* d_in, const int* in_sizes, int n_in,
                              void* d_out, int out_size) {
    const float* x          = (const float*)d_in[0];
    const int*   mask       = (const int*)  d_in[1];
    const float* Wp         = (const float*)d_in[3];
    const float* bp         = (const float*)d_in[4];
    const float* We2d       = (const float*)d_in[5];
    const float* be2d       = (const float*)d_in[6];
    const float* mask_token = (const float*)d_in[7];
    const float* pos_embed  = (const float*)d_in[8];
    const float* Wqkv       = (const float*)d_in[9];
    const float* bqkv       = (const float*)d_in[10];
    const float* Wo         = (const float*)d_in[11];
    const float* bo         = (const float*)d_in[12];
    const float* ln1g       = (const float*)d_in[13];
    const float* ln1b       = (const float*)d_in[14];
    const float* W1         = (const float*)d_in[15];
    const float* b1         = (const float*)d_in[16];
    const float* W2         = (const float*)d_in[17];
    const float* b2         = (const float*)d_in[18];
    const float* ln2g       = (const float*)d_in[19];
    const float* ln2b       = (const float*)d_in[20];
    const float* Wr         = (const float*)d_in[21];
    const float* br         = (const float*)d_in[22];

    float* out = (float*)d_out;
    float* rec = out;
    float* enc = out + (size_t)ROWS_N * OUTD;

    __half *p_patchh, *p_ench, *p_hh, *p_attnh, *p_ffnh, *p_wh;
    float  *p_dec, *p_h, *p_tmp, *p_qkv;
    cudaGetSymbolAddress((void**)&p_patchh, g_patchh);
    cudaGetSymbolAddress((void**)&p_ench,   g_ench);
    cudaGetSymbolAddress((void**)&p_dec,    g_dec);
    cudaGetSymbolAddress((void**)&p_h,      g_h);
    cudaGetSymbolAddress((void**)&p_hh,     g_hh);
    cudaGetSymbolAddress((void**)&p_tmp,    g_tmp);
    cudaGetSymbolAddress((void**)&p_attnh,  g_attnh);
    cudaGetSymbolAddress((void**)&p_qkv,    g_qkv);
    cudaGetSymbolAddress((void**)&p_ffnh,   g_ffnh);
    cudaGetSymbolAddress((void**)&p_wh,     g_wh);

    cudaFuncSetAttribute(attn_kernel, cudaFuncAttributeMaxDynamicSharedMemorySize, ATTN_SMEM);
    cudaFuncSetAttribute(gemm_tc_kernel, cudaFuncAttributeMaxDynamicSharedMemorySize, GEMM_SMEM);

    // weight prep: transpose to [N,K] + fp16 round
    launch_tr(Wp,   p_wh + WT_WP,  OUTD, ENC);
    launch_tr(We2d, p_wh + WT_E2D, ENC,  DEC);
    for (int l = 0; l < NL; l++) {
        launch_tr(Wqkv + (size_t)l * DEC * 3 * DEC, p_wh + WT_QKV + (size_t)l * 3 * DEC * DEC, DEC, 3 * DEC);
        launch_tr(Wo   + (size_t)l * DEC * DEC,     p_wh + WT_O   + (size_t)l * DEC * DEC,     DEC, DEC);
        launch_tr(W1   + (size_t)l * DEC * FFN,     p_wh + WT_W1  + (size_t)l * DEC * FFN,     DEC, FFN);
        launch_tr(W2   + (size_t)l * FFN * DEC,     p_wh + WT_W2  + (size_t)l * FFN * DEC,     FFN, DEC);
    }
    launch_tr(Wr, p_wh + WT_R, DEC, OUTD);

    scan_kernel<<<1, 64>>>(mask);
    patchify_kernel<<<ROWS_V, 256>>>(x);

    // encoder projection: fp32 out (to result) + fp16 copy for next GEMM
    launch_gemm(p_patchh, p_wh + WT_WP, bp, nullptr, enc, p_ench, ROWS_V, ENC, OUTD, 0);
    launch_gemm(p_ench, p_wh + WT_E2D, be2d, nullptr, p_dec, nullptr, ROWS_V, DEC, ENC, 0);
    assemble_kernel<<<ROWS_N, 128>>>(mask_token, pos_embed);

    for (int l = 0; l < NL; l++) {
        const __half* wh_qkv = p_wh + WT_QKV + (size_t)l * 3 * DEC * DEC;
        const __half* wh_o   = p_wh + WT_O   + (size_t)l * DEC * DEC;
        const __half* wh_1   = p_wh + WT_W1  + (size_t)l * DEC * FFN;
        const __half* wh_2   = p_wh + WT_W2  + (size_t)l * FFN * DEC;
        const float* bq  = bqkv + (size_t)l * 3 * DEC;
        const float* bol = bo   + (size_t)l * DEC;
        const float* b1l = b1   + (size_t)l * FFN;
        const float* b2l = b2   + (size_t)l * DEC;

        launch_gemm(p_hh, wh_qkv, bq, nullptr, p_qkv, nullptr, ROWS_N, 3 * DEC, DEC, 0);
        attn_kernel<<<B_ * NH, 256, ATTN_SMEM>>>();
        launch_gemm(p_attnh, wh_o, bol, p_h, p_tmp, nullptr, ROWS_N, DEC, DEC, 0);
        ln_kernel<<<ROWS_N, 128>>>(p_tmp, p_h, p_hh, ln1g + l * DEC, ln1b + l * DEC);
        launch_gemm(p_hh, wh_1, b1l, nullptr, nullptr, p_ffnh, ROWS_N, FFN, DEC, FLAG_GELU);
        launch_gemm(p_ffnh, wh_2, b2l, p_h, p_tmp, nullptr, ROWS_N, DEC, FFN, 0);
        ln_kernel<<<ROWS_N, 128>>>(p_tmp, p_h, p_hh, ln2g + l * DEC, ln2b + l * DEC);
    }

    launch_gemm(p_hh, p_wh + WT_R, br, nullptr, rec, nullptr, ROWS_N, OUTD, DEC, 0);
}

// round 11
// speedup vs baseline: 1.3188x; 1.0025x over previous
#include <cuda_runtime.h>
#include <cuda_fp16.h>
#include <cstdint>
#include <math.h>

// ---------------- problem constants ----------------
#define B_      64
#define V_      49
#define NPATCH  196
#define CIN     12
#define PSZ     16
#define IMG     224
#define ENC     768
#define DEC     512
#define NL      8
#define NH      16
#define HD      32
#define FFN     2048
#define OUTD    3072
#define ROWS_V  (B_ * V_)       // 3136
#define ROWS_N  (B_ * NPATCH)   // 12544

// ---------------- scratch ----------------
__device__ __half g_patchh[ROWS_V * OUTD];
__device__ __half g_ench  [ROWS_V * ENC];
__device__ float  g_dec   [ROWS_V * DEC];
__device__ float  g_h     [ROWS_N * DEC];
__device__ __half g_hh    [ROWS_N * DEC];
__device__ float  g_tmp   [ROWS_N * DEC];
__device__ __half g_attnh [ROWS_N * DEC];
__device__ __half g_qkvh  [ROWS_N * 3 * DEC];
__device__ __half g_ffnh  [ROWS_N * FFN];
__device__ __half g_wh    [29491200];        // fp16 weights, TRANSPOSED to [N,K]
__device__ int    g_visidx[B_ * V_];
__device__ int    g_src   [B_ * NPATCH];

// weight-scratch offsets (halfs)
#define WT_WP   0
#define WT_E2D  2359296
#define WT_QKV  2752512
#define WT_O    9043968
#define WT_W1   11141120
#define WT_W2   19529728
#define WT_R    27918336

// ---------------- helpers ----------------
__device__ __forceinline__ float gelu_exact(float v) {
    return 0.5f * v * (1.0f + erff(v * 0.7071067811865476f));
}
__device__ __forceinline__ void cp_async16(void* smem_dst, const void* gmem_src, bool pred) {
    uint32_t saddr = (uint32_t)__cvta_generic_to_shared(smem_dst);
    int sz = pred ? 16 : 0;
    asm volatile("cp.async.cg.shared.global [%0], [%1], 16, %2;\n"
                 :: "r"(saddr), "l"(gmem_src), "r"(sz));
}
__device__ __forceinline__ void mma_f16(float* c, const uint32_t* a, const uint32_t* b) {
    asm volatile(
        "mma.sync.aligned.m16n8k16.row.col.f32.f16.f16.f32 "
        "{%0,%1,%2,%3}, {%4,%5,%6,%7}, {%8,%9}, {%0,%1,%2,%3};"
        : "+f"(c[0]), "+f"(c[1]), "+f"(c[2]), "+f"(c[3])
        : "r"(a[0]), "r"(a[1]), "r"(a[2]), "r"(a[3]), "r"(b[0]), "r"(b[1]));
}
__device__ __forceinline__ void ldsm4(uint32_t* r, uint32_t saddr) {
    asm volatile("ldmatrix.sync.aligned.m8n8.x4.shared.b16 {%0,%1,%2,%3}, [%4];"
                 : "=r"(r[0]), "=r"(r[1]), "=r"(r[2]), "=r"(r[3]) : "r"(saddr));
}

// ---------------- weight prep: transpose [K,N]->[N,K] + fp16 round ----------------
__global__ void transpose_half(const float* __restrict__ src, __half* __restrict__ dst,
                               int K, int N) {
    __shared__ float t[32][33];
    int kb = blockIdx.y * 32, nb = blockIdx.x * 32;
    #pragma unroll
    for (int i = 0; i < 4; i++)
        t[threadIdx.y + 8 * i][threadIdx.x] =
            src[(size_t)(kb + threadIdx.y + 8 * i) * N + nb + threadIdx.x];
    __syncthreads();
    #pragma unroll
    for (int i = 0; i < 4; i++)
        dst[(size_t)(nb + threadIdx.y + 8 * i) * K + kb + threadIdx.x] =
            __float2half_rn(t[threadIdx.x][threadIdx.y + 8 * i]);
}

// ---------------- mask scan ----------------
__global__ void scan_kernel(const int* __restrict__ mask) {
    int b = threadIdx.x;
    if (b >= B_) return;
    int cnt = 0;
    for (int n = 0; n < NPATCH; n++) {
        int m = mask[b * NPATCH + n];
        if (m == 0) {
            if (cnt < V_) g_visidx[b * V_ + cnt] = n;
            g_src[b * NPATCH + n] = (cnt < V_) ? cnt : (V_ - 1);
            cnt++;
        } else {
            g_src[b * NPATCH + n] = -1;
        }
    }
    for (int c = cnt; c < V_; c++) g_visidx[b * V_ + c] = 0;
}

// ---------------- patchify -> fp16 ----------------
__global__ void patchify_kernel(const float* __restrict__ x) {
    int r  = blockIdx.x;
    int b  = r / V_;
    int n  = g_visidx[r];
    int hp = n / (IMG / PSZ);
    int wp = n % (IMG / PSZ);
    for (int f = threadIdx.x; f < OUTD; f += blockDim.x) {
        int c  = f >> 8;
        int ph = (f >> 4) & 15;
        int pw = f & 15;
        float v = x[((b * CIN + c) * IMG + hp * PSZ + ph) * IMG + wp * PSZ + pw];
        g_patchh[(size_t)r * OUTD + f] = __float2half_rn(v);
    }
}

// ---------------- assemble: fp32 residual + fp16 GEMM-A copy ----------------
__global__ void assemble_kernel(const float* __restrict__ mask_token,
                                const float* __restrict__ pos_embed) {
    int row = blockIdx.x;
    int b = row / NPATCH;
    int n = row % NPATCH;
    int s = g_src[row];
    const float4* src = (s >= 0)
        ? (const float4*)&g_dec[(b * V_ + s) * DEC]
        : (const float4*)mask_token;
    const float4* pos = (const float4*)&pos_embed[n * DEC];
    int t = threadIdx.x;
    float4 a = src[t], p = pos[t];
    float4 v = make_float4(a.x + p.x, a.y + p.y, a.z + p.z, a.w + p.w);
    ((float4*)&g_h[(size_t)row * DEC])[t] = v;
    __half2* hh = (__half2*)&g_hh[(size_t)row * DEC];
    hh[t * 2 + 0] = __floats2half2_rn(v.x, v.y);
    hh[t * 2 + 1] = __floats2half2_rn(v.z, v.w);
}

// ---------------- fp16 tensor-core GEMM ----------------
// C(MxN)[fp32, optional] (+Ch fp16 optional) = A(MxK,h) @ Wt(NxK,h)^T + bias [+resid] [gelu]
// 128x128 tile, BK=32, 4-stage, 8 warps (2m x 4n), warp tile 64x32.
#define BM 128
#define BN 128
#define BK 32
#define STRH 40                          // halfs per smem row (32 + pad 8) = 80 B, 16B-aligned
#define TILEH (128 * STRH)               // 5120 halfs per tile
#define STAGEH (2 * TILEH)               // A + B
#define NSTAGE 4
#define GEMM_SMEM (NSTAGE * STAGEH * 2)  // 81920 B
#define FLAG_GELU 1

__device__ __forceinline__ void gemm_load_stage(
    const __half* __restrict__ A, const __half* __restrict__ Wt,
    __half* sm, int s, int c, int bm, int bn, int M, int K, int t)
{
    __half* base = sm + s * STAGEH;
    int k0 = c * BK;
    #pragma unroll
    for (int i = 0; i < 4; i++) {
        int idx = t + (i << 8);              // 0..1023 (16B = 8 halfs each)
        int part = idx >> 9;                 // 0 = A, 1 = B
        int sub  = idx & 511;
        int row  = sub >> 2;                 // 0..127
        int c8   = sub & 3;                  // 0..3
        const __half* src;
        int ok = 1;
        if (part == 0) {
            int gr = bm + row;
            if (gr >= M) { ok = 0; gr = M - 1; }
            src = A + (size_t)gr * K + k0 + c8 * 8;
        } else {
            src = Wt + (size_t)(bn + row) * K + k0 + c8 * 8;
        }
        cp_async16(base + part * TILEH + row * STRH + c8 * 8, src, ok);
    }
    asm volatile("cp.async.commit_group;\n");
}

__global__ __launch_bounds__(256, 2) void gemm_tc_kernel(
    const __half* __restrict__ A, const __half* __restrict__ Wt,
    const float* __restrict__ bias, const float* __restrict__ resid,
    float* __restrict__ C, __half* __restrict__ Ch,
    int M, int N, int K, int flags)
{
    extern __shared__ __half sm[];

    const int t = threadIdx.x;
    const int bn = blockIdx.x * BN;
    const int bm = blockIdx.y * BM;
    const int warp = t >> 5, lane = t & 31;
    const int wm = warp >> 2, wn = warp & 3;     // 2 x 4 warps, warp tile 64x32
    const int lq = lane >> 2, lr = lane & 3;
    const int g  = lane >> 3;                    // ldmatrix group 0..3
    const int gr = lane & 7;

    float acc[4][4][4] = {};

    const int nch = K / BK;
    gemm_load_stage(A, Wt, sm, 0, 0, bm, bn, M, K, t);
    if (nch > 1) gemm_load_stage(A, Wt, sm, 1, 1, bm, bn, M, K, t);
    if (nch > 2) gemm_load_stage(A, Wt, sm, 2, 2, bm, bn, M, K, t);

    // ldmatrix per-thread base offsets (halfs)
    const int a_off = (wm * 64 + (g & 1) * 8 + gr) * STRH + (g >> 1) * 8;
    const int b_off = (wn * 32 + g * 8 + gr) * STRH;

    for (int c = 0; c < nch; c++) {
        int s = c & (NSTAGE - 1);
        if (c + 2 < nch)      asm volatile("cp.async.wait_group 2;\n");
        else if (c + 1 < nch) asm volatile("cp.async.wait_group 1;\n");
        else                  asm volatile("cp.async.wait_group 0;\n");
        __syncthreads();
        if (c + 3 < nch)
            gemm_load_stage(A, Wt, sm, (c + 3) & (NSTAGE - 1), c + 3, bm, bn, M, K, t);

        const __half* Ab = sm + s * STAGEH;
        const __half* Bb = Ab + TILEH;
        uint32_t a_base = (uint32_t)__cvta_generic_to_shared(Ab + a_off);
        uint32_t b_base = (uint32_t)__cvta_generic_to_shared(Bb + b_off);

        #pragma unroll
        for (int ks = 0; ks < 2; ks++) {          // two k16 steps per BK=32 chunk
            const int kh = ks * 16;
            uint32_t af[4][4];
            uint32_t b0[4], b1[4];
            #pragma unroll
            for (int mi = 0; mi < 4; mi++)
                ldsm4(af[mi], a_base + (mi * 16 * STRH + kh) * 2);
            ldsm4(b0, b_base + (kh + 0) * 2);     // k 0-7 of this step, 4 n-tiles
            ldsm4(b1, b_base + (kh + 8) * 2);     // k 8-15
            #pragma unroll
            for (int mi = 0; mi < 4; mi++)
                #pragma unroll
                for (int ni = 0; ni < 4; ni++) {
                    uint32_t bf[2] = { b0[ni], b1[ni] };
                    mma_f16(acc[mi][ni], af[mi], bf);
                }
        }
        __syncthreads();
    }

    const bool dogelu = (flags & FLAG_GELU) != 0;

    #pragma unroll
    for (int mi = 0; mi < 4; mi++) {
        int r0 = bm + wm * 64 + mi * 16 + lq;
        #pragma unroll
        for (int ni = 0; ni < 4; ni++) {
            int col = bn + wn * 32 + ni * 8 + lr * 2;
            float bx = bias[col], by = bias[col + 1];
            float* a4 = acc[mi][ni];
            #pragma unroll
            for (int half = 0; half < 2; half++) {
                int r = r0 + half * 8;
                if (r >= M) continue;
                float vx = a4[half * 2 + 0] + bx;
                float vy = a4[half * 2 + 1] + by;
                if (resid) {
                    const float* rr = resid + (size_t)r * N + col;
                    vx += rr[0]; vy += rr[1];
                }
                if (dogelu) { vx = gelu_exact(vx); vy = gelu_exact(vy); }
                if (C)
                    *(float2*)(C + (size_t)r * N + col) = make_float2(vx, vy);
                if (Ch)
                    *(__half2*)(Ch + (size_t)r * N + col) = __floats2half2_rn(vx, vy);
            }
        }
    }
}

// ---------------- layernorm: fp32 out + fp16 out ----------------
__global__ __launch_bounds__(128) void ln_kernel(
    const float* __restrict__ in, float* __restrict__ out, __half* __restrict__ outh,
    const float* __restrict__ gamma, const float* __restrict__ beta)
{
    __shared__ float red[8];
    int row = blockIdx.x;
    int t = threadIdx.x;
    float4 v = ((const float4*)(in + (size_t)row * DEC))[t];
    float s  = v.x + v.y + v.z + v.w;
    float sq = v.x * v.x + v.y * v.y + v.z * v.z + v.w * v.w;
    #pragma unroll
    for (int off = 16; off > 0; off >>= 1) {
        s  += __shfl_xor_sync(0xffffffff, s,  off);
        sq += __shfl_xor_sync(0xffffffff, sq, off);
    }
    int w = t >> 5;
    if ((t & 31) == 0) { red[w] = s; red[4 + w] = sq; }
    __syncthreads();
    s  = red[0] + red[1] + red[2] + red[3];
    sq = red[4] + red[5] + red[6] + red[7];
    float mu = s * (1.0f / DEC);
    float var = sq * (1.0f / DEC) - mu * mu;
    float rstd = rsqrtf(var + 1e-5f);
    float4 g = ((const float4*)gamma)[t];
    float4 b = ((const float4*)beta)[t];
    float4 o;
    o.x = (v.x - mu) * rstd * g.x + b.x;
    o.y = (v.y - mu) * rstd * g.y + b.y;
    o.z = (v.z - mu) * rstd * g.z + b.z;
    o.w = (v.w - mu) * rstd * g.w + b.w;
    ((float4*)(out + (size_t)row * DEC))[t] = o;
    __half2* hh = (__half2*)(outh + (size_t)row * DEC);
    hh[t * 2 + 0] = __floats2half2_rn(o.x, o.y);
    hh[t * 2 + 1] = __floats2half2_rn(o.z, o.w);
}

// ---------------- attention (fp16 qkv input) ----------------
#define KSTRIDE 33
#define SM_K 0
#define SM_V (NPATCH * KSTRIDE)
#define SM_P (SM_V + NPATCH * HD)
#define ATTN_SMEM ((SM_P + 8 * NPATCH) * 4)

__global__ __launch_bounds__(256) void attn_kernel() {
    extern __shared__ float smf[];
    float* Ksm = smf + SM_K;
    float* Vsm = smf + SM_V;
    float* Psm = smf + SM_P;

    int bh = blockIdx.x;
    int b = bh >> 4;
    int h = bh & 15;
    const __half* qkv = g_qkvh + (size_t)b * (NPATCH * 3 * DEC);
    int tid = threadIdx.x;

    for (int idx = tid; idx < NPATCH * HD; idx += 256) {
        int j = idx >> 5, d = idx & 31;
        Ksm[j * KSTRIDE + d] = __half2float(qkv[j * (3 * DEC) + DEC     + h * HD + d]);
        Vsm[j * HD      + d] = __half2float(qkv[j * (3 * DEC) + 2 * DEC + h * HD + d]);
    }
    __syncthreads();

    int warp = tid >> 5, lane = tid & 31;
    const float scale = 0.17677669529663687f;

    for (int i = warp; i < NPATCH; i += 8) {
        const __half* q = qkv + i * (3 * DEC) + h * HD;
        float qr[HD];
        #pragma unroll
        for (int kk = 0; kk < HD; kk++) qr[kk] = __half2float(q[kk]);

        float s[7];
        float mx = -1e30f;
        #pragma unroll
        for (int jj = 0; jj < 7; jj++) {
            int j = jj * 32 + lane;
            float acc = -1e30f;
            if (j < NPATCH) {
                acc = 0.f;
                #pragma unroll
                for (int kk = 0; kk < HD; kk++) acc += qr[kk] * Ksm[j * KSTRIDE + kk];
                acc *= scale;
            }
            s[jj] = acc;
            mx = fmaxf(mx, acc);
        }
        #pragma unroll
        for (int off = 16; off > 0; off >>= 1)
            mx = fmaxf(mx, __shfl_xor_sync(0xffffffff, mx, off));

        float sum = 0.f;
        #pragma unroll
        for (int jj = 0; jj < 7; jj++) {
            int j = jj * 32 + lane;
            float p = (j < NPATCH) ? __expf(s[jj] - mx) : 0.f;
            if (j < NPATCH) Psm[warp * NPATCH + j] = p;
            sum += p;
        }
        #pragma unroll
        for (int off = 16; off > 0; off >>= 1)
            sum += __shfl_xor_sync(0xffffffff, sum, off);
        float inv = 1.0f / sum;
        __syncwarp();

        const float* pp = Psm + warp * NPATCH;
        float a0 = 0.f, a1 = 0.f, a2 = 0.f, a3 = 0.f;
        for (int j = 0; j < NPATCH; j += 4) {
            a0 += pp[j]     * Vsm[j * HD + lane];
            a1 += pp[j + 1] * Vsm[(j + 1) * HD + lane];
            a2 += pp[j + 2] * Vsm[(j + 2) * HD + lane];
            a3 += pp[j + 3] * Vsm[(j + 3) * HD + lane];
        }
        float acc = (a0 + a1) + (a2 + a3);
        g_attnh[((size_t)b * NPATCH + i) * DEC + h * HD + lane] = __float2half_rn(acc * inv);
        __syncwarp();
    }
}

// ---------------- host launchers ----------------
static inline void launch_gemm(const __half* A, const __half* Wt, const float* bias,
                               const float* resid, float* C, __half* Ch,
                               int M, int N, int K, int flags) {
    dim3 grid(N / BN, (M + BM - 1) / BM);
    gemm_tc_kernel<<<grid, 256, GEMM_SMEM>>>(A, Wt, bias, resid, C, Ch, M, N, K, flags);
}
static inline void launch_tr(const float* src, __half* dst, int K, int N) {
    dim3 grid(N / 32, K / 32), blk(32, 8);
    transpose_half<<<grid, blk>>>(src, dst, K, N);
}

extern "C" void kernel_launch(void* const* d_in, const int* in_sizes, int n_in,
                              void* d_out, int out_size) {
    const float* x          = (const float*)d_in[0];
    const int*   mask       = (const int*)  d_in[1];
    const float* Wp         = (const float*)d_in[3];
    const float* bp         = (const float*)d_in[4];
    const float* We2d       = (const float*)d_in[5];
    const float* be2d       = (const float*)d_in[6];
    const float* mask_token = (const float*)d_in[7];
    const float* pos_embed  = (const float*)d_in[8];
    const float* Wqkv       = (const float*)d_in[9];
    const float* bqkv       = (const float*)d_in[10];
    const float* Wo         = (const float*)d_in[11];
    const float* bo         = (const float*)d_in[12];
    const float* ln1g       = (const float*)d_in[13];
    const float* ln1b       = (const float*)d_in[14];
    const float* W1         = (const float*)d_in[15];
    const float* b1         = (const float*)d_in[16];
    const float* W2         = (const float*)d_in[17];
    const float* b2         = (const float*)d_in[18];
    const float* ln2g       = (const float*)d_in[19];
    const float* ln2b       = (const float*)d_in[20];
    const float* Wr         = (const float*)d_in[21];
    const float* br         = (const float*)d_in[22];

    float* out = (float*)d_out;
    float* rec = out;
    float* enc = out + (size_t)ROWS_N * OUTD;

    __half *p_patchh, *p_ench, *p_hh, *p_attnh, *p_qkvh, *p_ffnh, *p_wh;
    float  *p_dec, *p_h, *p_tmp;
    cudaGetSymbolAddress((void**)&p_patchh, g_patchh);
    cudaGetSymbolAddress((void**)&p_ench,   g_ench);
    cudaGetSymbolAddress((void**)&p_dec,    g_dec);
    cudaGetSymbolAddress((void**)&p_h,      g_h);
    cudaGetSymbolAddress((void**)&p_hh,     g_hh);
    cudaGetSymbolAddress((void**)&p_tmp,    g_tmp);
    cudaGetSymbolAddress((void**)&p_attnh,  g_attnh);
    cudaGetSymbolAddress((void**)&p_qkvh,   g_qkvh);
    cudaGetSymbolAddress((void**)&p_ffnh,   g_ffnh);
    cudaGetSymbolAddress((void**)&p_wh,     g_wh);

    cudaFuncSetAttribute(attn_kernel, cudaFuncAttributeMaxDynamicSharedMemorySize, ATTN_SMEM);
    cudaFuncSetAttribute(gemm_tc_kernel, cudaFuncAttributeMaxDynamicSharedMemorySize, GEMM_SMEM);

    // weight prep: transpose to [N,K] + fp16 round
    launch_tr(Wp,   p_wh + WT_WP,  OUTD, ENC);
    launch_tr(We2d, p_wh + WT_E2D, ENC,  DEC);
    for (int l = 0; l < NL; l++) {
        launch_tr(Wqkv + (size_t)l * DEC * 3 * DEC, p_wh + WT_QKV + (size_t)l * 3 * DEC * DEC, DEC, 3 * DEC);
        launch_tr(Wo   + (size_t)l * DEC * DEC,     p_wh + WT_O   + (size_t)l * DEC * DEC,     DEC, DEC);
        launch_tr(W1   + (size_t)l * DEC * FFN,     p_wh + WT_W1  + (size_t)l * DEC * FFN,     DEC, FFN);
        launch_tr(W2   + (size_t)l * FFN * DEC,     p_wh + WT_W2  + (size_t)l * FFN * DEC,     FFN, DEC);
    }
    launch_tr(Wr, p_wh + WT_R, DEC, OUTD);

    scan_kernel<<<1, 64>>>(mask);
    patchify_kernel<<<ROWS_V, 256>>>(x);

    // encoder projection: fp32 out (to result) + fp16 copy for next GEMM
    launch_gemm(p_patchh, p_wh + WT_WP, bp, nullptr, enc, p_ench, ROWS_V, ENC, OUTD, 0);
    launch_gemm(p_ench, p_wh + WT_E2D, be2d, nullptr, p_dec, nullptr, ROWS_V, DEC, ENC, 0);
    assemble_kernel<<<ROWS_N, 128>>>(mask_token, pos_embed);

    for (int l = 0; l < NL; l++) {
        const __half* wh_qkv = p_wh + WT_QKV + (size_t)l * 3 * DEC * DEC;
        const __half* wh_o   = p_wh + WT_O   + (size_t)l * DEC * DEC;
        const __half* wh_1   = p_wh + WT_W1  + (size_t)l * DEC * FFN;
        const __half* wh_2   = p_wh + WT_W2  + (size_t)l * FFN * DEC;
        const float* bq  = bqkv + (size_t)l * 3 * DEC;
        const float* bol = bo   + (size_t)l * DEC;
        const float* b1l = b1   + (size_t)l * FFN;
        const float* b2l = b2   + (size_t)l * DEC;

        launch_gemm(p_hh, wh_qkv, bq, nullptr, nullptr, p_qkvh, ROWS_N, 3 * DEC, DEC, 0);
        attn_kernel<<<B_ * NH, 256, ATTN_SMEM>>>();
        launch_gemm(p_attnh, wh_o, bol, p_h, p_tmp, nullptr, ROWS_N, DEC, DEC, 0);
        ln_kernel<<<ROWS_N, 128>>>(p_tmp, p_h, p_hh, ln1g + l * DEC, ln1b + l * DEC);
        launch_gemm(p_hh, wh_1, b1l, nullptr, nullptr, p_ffnh, ROWS_N, FFN, DEC, FLAG_GELU);
        launch_gemm(p_ffnh, wh_2, b2l, p_h, p_tmp, nullptr, ROWS_N, DEC, FFN, 0);
        ln_kernel<<<ROWS_N, 128>>>(p_tmp, p_h, p_hh, ln2g + l * DEC, ln2b + l * DEC);
    }

    launch_gemm(p_hh, p_wh + WT_R, br, nullptr, rec, nullptr, ROWS_N, OUTD, DEC, 0);
}